// round 16
// baseline (speedup 1.0000x reference)
#include <cuda_runtime.h>
#include <cuda_fp16.h>
#include <cstdint>
#include <cstddef>
#include <math.h>

// ============================================================================
// Problem dims
// ============================================================================
#define PP   54
#define BBT  2048
#define DDIM 512

static constexpr size_t XT = (size_t)BBT * PP * DDIM;   // 56,623,104
static constexpr size_t WE = (size_t)PP * DDIM * DDIM;  // 14,155,776

static constexpr int BM = 128, BN = 128, BK = 64, STAGES = 3;  // BK in halves (128B rows)
static constexpr int NTH = 128;                                // 4 warps, 2x2, warp tile 64x64
static constexpr int STAGE_BYTES = (BM + BN) * BK * 2;         // 32768
static constexpr int SMEM_BYTES  = STAGE_BYTES * STAGES;       // 98304 -> 2 CTAs/SM

// ============================================================================
// Device-global scratch
// ============================================================================
__device__ __align__(16) __half g_xh[XT];   // fp16 x, transposed to [P,B,D]
__device__ __align__(16) __half g_h[XT];    // fp16 gelu(h), [P,B,D]
__device__ __align__(16) __half g_w1[WE];   // fp16 W1 [P,D,D]
__device__ __align__(16) __half g_w2[WE];   // fp16 W2 [P,D,D]
__device__ float2 g_stats[(size_t)BBT * PP * 8];  // per-row, per-64col-slice (sum, sumsq)

// ============================================================================
// PTX helpers (all pre-Hopper: compile for compute_103 without 'a' features)
// ============================================================================
__device__ __forceinline__ uint32_t s2u(const void* p) {
    uint32_t a;
    asm("{ .reg .u64 t; cvta.to.shared.u64 t, %1; cvt.u32.u64 %0, t; }" : "=r"(a) : "l"(p));
    return a;
}
__device__ __forceinline__ void cp16(uint32_t d, const void* s) {
    asm volatile("cp.async.cg.shared.global [%0], [%1], 16;" :: "r"(d), "l"(s));
}
__device__ __forceinline__ void cp_commit() { asm volatile("cp.async.commit_group;"); }
template <int N>
__device__ __forceinline__ void cp_wait() { asm volatile("cp.async.wait_group %0;" :: "n"(N)); }

__device__ __forceinline__ void ldm4(uint32_t r[4], uint32_t addr) {
    asm volatile("ldmatrix.sync.aligned.m8n8.x4.shared.b16 {%0,%1,%2,%3}, [%4];"
                 : "=r"(r[0]), "=r"(r[1]), "=r"(r[2]), "=r"(r[3]) : "r"(addr));
}

// fp16 MMA, fp32 accumulator: m16n8k16
__device__ __forceinline__ void mma16(float c[4], const uint32_t a[4], const uint32_t b[2]) {
    asm volatile(
        "mma.sync.aligned.m16n8k16.row.col.f32.f16.f16.f32 "
        "{%0,%1,%2,%3}, {%4,%5,%6,%7}, {%8,%9}, {%0,%1,%2,%3};"
        : "+f"(c[0]), "+f"(c[1]), "+f"(c[2]), "+f"(c[3])
        : "r"(a[0]), "r"(a[1]), "r"(a[2]), "r"(a[3]), "r"(b[0]), "r"(b[1]));
}

// ============================================================================
// Core: C[128x128] = A[128x512] * B[128x512]^T (fp16 K-major, fp32 acc)
// 4 warps 2(m) x 2(n); warp tile 64x64; acc[4 mfrag][8 nfrag][4]
// (R8-proven version: hoisted load addressing, frag double-buffer, STAGES=3)
// ============================================================================
__device__ __forceinline__ void gemm_core(const __half* __restrict__ Ab,
                                          const __half* __restrict__ Bb,
                                          float acc[4][8][4], char* smem) {
    int tid = threadIdx.x;
    uint32_t smu = s2u(smem);
    int r0 = tid >> 3, seg = tid & 7;

    const __half* aPtr = Ab + (size_t)r0 * DDIM + seg * 8;
    const __half* bPtr = Bb + (size_t)r0 * DDIM + seg * 8;
    uint32_t dstA = smu + (uint32_t)(r0 * 128 + ((seg ^ (r0 & 7)) << 4));
    uint32_t dstB = dstA + BM * 128;

    auto load = [&](int stage, int k0) {
        uint32_t so = (uint32_t)stage * STAGE_BYTES;
#pragma unroll
        for (int t = 0; t < 8; ++t)
            cp16(dstA + so + t * 2048, aPtr + k0 + (size_t)t * 16 * DDIM);
#pragma unroll
        for (int t = 0; t < 8; ++t)
            cp16(dstB + so + t * 2048, bPtr + k0 + (size_t)t * 16 * DDIM);
    };

    load(0, 0);  cp_commit();
    load(1, BK); cp_commit();

    int lane = tid & 31, warp = tid >> 5;
    int wy = warp & 1, wx = warp >> 1;
    int lane7 = lane & 7, sub = lane >> 3;
    int aSel = sub >> 1, bSel = sub & 1;  // which 16B seg (lo/hi of k16) this thread fetches

    // ldmatrix per-thread row bases. row&7 == lane7 for every fragment row.
    uint32_t aBase[4], bBase[4];
#pragma unroll
    for (int i = 0; i < 4; ++i)
        aBase[i] = (uint32_t)(wy * 64 + 16 * i + lane7 + 8 * (sub & 1)) * 128;
#pragma unroll
    for (int jp = 0; jp < 4; ++jp)
        bBase[jp] = (uint32_t)(BM * 128) +
                    (uint32_t)(wx * 64 + 16 * jp + 8 * (sub >> 1) + lane7) * 128;

    int ld = 2, ls = 2, cs = 0;
#pragma unroll 1
    for (int kc = 0; kc < DDIM / BK; ++kc) {
        cp_wait<STAGES - 2>();
        __syncthreads();  // stage kc ready; all warps done with stage being overwritten
        if (ld < DDIM / BK) {
            load(ls, ld * BK);
            ++ld; if (++ls == STAGES) ls = 0;
        }
        cp_commit();
        uint32_t sbu = smu + cs * STAGE_BYTES;
        if (++cs == STAGES) cs = 0;

        uint32_t a[2][4][4], b[2][4][4];
        {
            uint32_t swA = (uint32_t)((aSel ^ lane7) << 4);
            uint32_t swB = (uint32_t)((bSel ^ lane7) << 4);
#pragma unroll
            for (int i = 0; i < 4; ++i) ldm4(a[0][i], sbu + aBase[i] + swA);
#pragma unroll
            for (int jp = 0; jp < 4; ++jp) ldm4(b[0][jp], sbu + bBase[jp] + swB);
        }
#pragma unroll
        for (int ks = 0; ks < 4; ++ks) {
            int cb = ks & 1, nb = cb ^ 1;
            if (ks < 3) {  // prefetch ks+1 fragments; overlaps the MMA block below
                uint32_t swA = (uint32_t)(((2 * (ks + 1) + aSel) ^ lane7) << 4);
                uint32_t swB = (uint32_t)(((2 * (ks + 1) + bSel) ^ lane7) << 4);
#pragma unroll
                for (int i = 0; i < 4; ++i) ldm4(a[nb][i], sbu + aBase[i] + swA);
#pragma unroll
                for (int jp = 0; jp < 4; ++jp) ldm4(b[nb][jp], sbu + bBase[jp] + swB);
            }
#pragma unroll
            for (int i = 0; i < 4; ++i)
#pragma unroll
                for (int j = 0; j < 8; ++j)
                    mma16(acc[i][j], a[cb][i], &b[cb][j >> 1][(j & 1) * 2]);
        }
    }
}

// ============================================================================
// GEMM1: h = gelu(x @ W1^T + b1) -> g_h [P,B,D] fp16
// g_h stores use evict-first (.cs): touch-once stream, keeps W tiles L2-hot.
// ============================================================================
__global__ void __launch_bounds__(NTH, 2)
gemm1_kernel(const float* __restrict__ b1) {
    extern __shared__ char smem[];
    int p = blockIdx.z, m0 = blockIdx.y * BM, n0 = blockIdx.x * BN;
    const __half* Ab = g_xh + ((size_t)p * BBT + m0) * DDIM;
    const __half* Bb = g_w1 + (size_t)p * DDIM * DDIM + (size_t)n0 * DDIM;

    float acc[4][8][4];
#pragma unroll
    for (int i = 0; i < 4; ++i)
#pragma unroll
        for (int j = 0; j < 8; ++j)
#pragma unroll
            for (int k = 0; k < 4; ++k) acc[i][j][k] = 0.0f;

    gemm_core(Ab, Bb, acc, smem);

    int lane = threadIdx.x & 31, warp = threadIdx.x >> 5;
    int wy = warp & 1, wx = warp >> 1, q = lane >> 2, t4 = lane & 3;
    const float* bias = b1 + p * DDIM + n0 + wx * 64;
#pragma unroll
    for (int i = 0; i < 4; ++i)
#pragma unroll
        for (int h = 0; h < 2; ++h) {
            int row = m0 + wy * 64 + 16 * i + q + 8 * h;  // batch index b
            __half* hrow = g_h + ((size_t)p * BBT + row) * DDIM + n0 + wx * 64;
#pragma unroll
            for (int j = 0; j < 8; ++j) {
                int col = 8 * j + 2 * t4;
                float2 bv = *reinterpret_cast<const float2*>(bias + col);
                float v0 = acc[i][j][2 * h]     + bv.x;
                float v1 = acc[i][j][2 * h + 1] + bv.y;
                float g0 = 0.5f * v0 * (1.0f + erff(v0 * 0.70710678118654752f));
                float g1 = 0.5f * v1 * (1.0f + erff(v1 * 0.70710678118654752f));
                __half2 hv = __floats2half2_rn(g0, g1);
                __stcs(reinterpret_cast<float*>(hrow + col),
                       __uint_as_float(*reinterpret_cast<uint32_t*>(&hv)));
            }
        }
}

// ============================================================================
// GEMM2: d_out = h @ W2^T + b2 + x (unnormalized), plus per-64col LN stats.
// Touch-once streams (x residual, out) use evict-first hints.
// ============================================================================
__global__ void __launch_bounds__(NTH, 2)
gemm2_kernel(const float* __restrict__ x, const float* __restrict__ b2,
             float* __restrict__ out) {
    extern __shared__ char smem[];
    int p = blockIdx.z, m0 = blockIdx.y * BM, n0 = blockIdx.x * BN;
    const __half* Ab = g_h  + ((size_t)p * BBT + m0) * DDIM;
    const __half* Bb = g_w2 + (size_t)p * DDIM * DDIM + (size_t)n0 * DDIM;

    float acc[4][8][4];
#pragma unroll
    for (int i = 0; i < 4; ++i)
#pragma unroll
        for (int j = 0; j < 8; ++j)
#pragma unroll
            for (int k = 0; k < 4; ++k) acc[i][j][k] = 0.0f;

    gemm_core(Ab, Bb, acc, smem);

    int lane = threadIdx.x & 31, warp = threadIdx.x >> 5;
    int wy = warp & 1, wx = warp >> 1, q = lane >> 2, t4 = lane & 3;
    const float* bias = b2 + p * DDIM + n0 + wx * 64;
    int slice = blockIdx.x * 2 + wx;  // 8 slices of 64 cols per output row
#pragma unroll
    for (int i = 0; i < 4; ++i)
#pragma unroll
        for (int h = 0; h < 2; ++h) {
            int row = m0 + wy * 64 + 16 * i + q + 8 * h;  // batch index b
            size_t ro = (size_t)row * PP + p;             // output row id
            const float* xr = x + ro * DDIM + n0 + wx * 64;
            float* orow = out + ro * DDIM + n0 + wx * 64;
            float s = 0.0f, ss = 0.0f;
#pragma unroll
            for (int j = 0; j < 8; ++j) {
                int col = 8 * j + 2 * t4;
                float2 xv = __ldcs(reinterpret_cast<const float2*>(xr + col));
                float2 bv = *reinterpret_cast<const float2*>(bias + col);
                float v0 = acc[i][j][2 * h]     + bv.x + xv.x;
                float v1 = acc[i][j][2 * h + 1] + bv.y + xv.y;
                __stcs(reinterpret_cast<float2*>(orow + col), make_float2(v0, v1));
                s += v0 + v1;
                ss += v0 * v0 + v1 * v1;
            }
            s  += __shfl_xor_sync(0xffffffffu, s, 1);
            s  += __shfl_xor_sync(0xffffffffu, s, 2);
            ss += __shfl_xor_sync(0xffffffffu, ss, 1);
            ss += __shfl_xor_sync(0xffffffffu, ss, 2);
            if (t4 == 0) g_stats[ro * 8 + slice] = make_float2(s, ss);
        }
}

// ============================================================================
// LN finalize: normalize d_out in place using precomputed stats.
// Row data is touch-once both directions -> .cs load and store.
// ============================================================================
__global__ void __launch_bounds__(256)
ln_kernel(float* __restrict__ out, const float* __restrict__ gamma,
          const float* __restrict__ beta) {
    int warp = threadIdx.x >> 5, lane = threadIdx.x & 31;
    size_t r = (size_t)blockIdx.x * 8 + warp;
    float s = 0.0f, ss = 0.0f;
    if (lane < 8) {
        float2 st = g_stats[r * 8 + lane];
        s = st.x; ss = st.y;
    }
#pragma unroll
    for (int d = 1; d < 8; d <<= 1) {
        s  += __shfl_xor_sync(0xffffffffu, s, d);
        ss += __shfl_xor_sync(0xffffffffu, ss, d);
    }
    s  = __shfl_sync(0xffffffffu, s, 0);
    ss = __shfl_sync(0xffffffffu, ss, 0);
    float mu = s * (1.0f / 512.0f);
    float rstd = rsqrtf(ss * (1.0f / 512.0f) - mu * mu + 1e-5f);

    float* row = out + r * DDIM;
#pragma unroll
    for (int c = 0; c < 4; ++c) {
        int idx = c * 128 + lane * 4;
        float4 v = __ldcs(reinterpret_cast<const float4*>(row + idx));
        float4 g = *reinterpret_cast<const float4*>(gamma + idx);
        float4 b = *reinterpret_cast<const float4*>(beta + idx);
        float4 o;
        o.x = (v.x - mu) * rstd * g.x + b.x;
        o.y = (v.y - mu) * rstd * g.y + b.y;
        o.z = (v.z - mu) * rstd * g.z + b.z;
        o.w = (v.w - mu) * rstd * g.w + b.w;
        __stcs(reinterpret_cast<float4*>(row + idx), o);
    }
}

// ============================================================================
// Single merged converter: W1/W2 fp32->fp16 and x fp32->fp16 [B,P,D]->[P,B,D].
// All streams touch-once -> .cs both directions.
// ============================================================================
__device__ __forceinline__ float2 pack4h_f2(float4 v) {
    __half2 h01 = __floats2half2_rn(v.x, v.y);
    __half2 h23 = __floats2half2_rn(v.z, v.w);
    float2 r;
    r.x = __uint_as_float(*reinterpret_cast<uint32_t*>(&h01));
    r.y = __uint_as_float(*reinterpret_cast<uint32_t*>(&h23));
    return r;
}

__global__ void cvt_all_kernel(const float4* __restrict__ x4,
                               const float4* __restrict__ w1,
                               const float4* __restrict__ w2) {
    const size_t NW = WE / 4;           // 3,538,944 per W array
    const size_t NX = XT / 4;           // 14,155,776
    size_t total = NW + NX;             // w-pairs first, then x
    size_t stride = (size_t)gridDim.x * blockDim.x;
    for (size_t t = (size_t)blockIdx.x * blockDim.x + threadIdx.x; t < total; t += stride) {
        if (t < NW) {
            __stcs(reinterpret_cast<float2*>(g_w1 + t * 4), pack4h_f2(__ldcs(w1 + t)));
            __stcs(reinterpret_cast<float2*>(g_w2 + t * 4), pack4h_f2(__ldcs(w2 + t)));
        } else {
            size_t u = t - NW;
            size_t d4 = u & (DDIM / 4 - 1);       // 0..127
            size_t b  = (u >> 7) & (BBT - 1);     // 0..2047
            size_t p  = u >> 18;                  // 0..53
            float4 v = __ldcs(x4 + (b * PP + p) * (DDIM / 4) + d4);
            __stcs(reinterpret_cast<float2*>(g_xh + (p * BBT + b) * DDIM + d4 * 4),
                   pack4h_f2(v));
        }
    }
}

// ============================================================================
// kernel_launch
// ============================================================================
extern "C" void kernel_launch(void* const* d_in, const int* in_sizes, int n_in,
                              void* d_out, int out_size) {
    const float* x     = (const float*)d_in[0];
    const float* W1    = (const float*)d_in[1];
    const float* b1    = (const float*)d_in[2];
    const float* W2    = (const float*)d_in[3];
    const float* b2    = (const float*)d_in[4];
    const float* gamma = (const float*)d_in[5];
    const float* beta  = (const float*)d_in[6];
    float* out = (float*)d_out;

    cudaFuncSetAttribute(gemm1_kernel, cudaFuncAttributeMaxDynamicSharedMemorySize, SMEM_BYTES);
    cudaFuncSetAttribute(gemm2_kernel, cudaFuncAttributeMaxDynamicSharedMemorySize, SMEM_BYTES);

    cvt_all_kernel<<<2368, 256>>>(reinterpret_cast<const float4*>(x),
                                  reinterpret_cast<const float4*>(W1),
                                  reinterpret_cast<const float4*>(W2));

    // x fastest = n-tile: 4 CTAs share each A tile; one patch's W (512KB fp16) L2-hot
    dim3 grid(DDIM / BN, BBT / BM, PP);  // (4, 16, 54)
    gemm1_kernel<<<grid, NTH, SMEM_BYTES>>>(b1);
    gemm2_kernel<<<grid, NTH, SMEM_BYTES>>>(x, b2, out);

    ln_kernel<<<(BBT * PP) / 8, 256>>>(out, gamma, beta);
}

// round 17
// speedup vs baseline: 1.4616x; 1.4616x over previous
#include <cuda_runtime.h>
#include <cuda_fp16.h>
#include <cstdint>
#include <cstddef>
#include <math.h>

// ============================================================================
// Problem dims
// ============================================================================
#define PP   54
#define BBT  2048
#define DDIM 512

static constexpr size_t XT = (size_t)BBT * PP * DDIM;   // 56,623,104
static constexpr size_t WE = (size_t)PP * DDIM * DDIM;  // 14,155,776

static constexpr int BM = 128, BN = 128, BK = 64, STAGES = 3;  // BK in halves (128B rows)
static constexpr int NTH = 128;                                // 4 warps, 2x2, warp tile 64x64
static constexpr int STAGE_BYTES = (BM + BN) * BK * 2;         // 32768
static constexpr int SMEM_BYTES  = STAGE_BYTES * STAGES;       // 98304 -> 2 CTAs/SM

// ============================================================================
// Device-global scratch
// ============================================================================
__device__ __align__(16) __half g_xh[XT];   // fp16 x, transposed to [P,B,D]
__device__ __align__(16) __half g_h[XT];    // fp16 gelu(h), [P,B,D]
__device__ __align__(16) __half g_w1[WE];   // fp16 W1 [P,D,D]
__device__ __align__(16) __half g_w2[WE];   // fp16 W2 [P,D,D]
__device__ float2 g_stats[(size_t)BBT * PP * 8];  // per-row, per-64col-slice (sum, sumsq)

// ============================================================================
// PTX helpers (all pre-Hopper: compile for compute_103 without 'a' features)
// ============================================================================
__device__ __forceinline__ uint32_t s2u(const void* p) {
    uint32_t a;
    asm("{ .reg .u64 t; cvta.to.shared.u64 t, %1; cvt.u32.u64 %0, t; }" : "=r"(a) : "l"(p));
    return a;
}
__device__ __forceinline__ void cp16(uint32_t d, const void* s) {
    asm volatile("cp.async.cg.shared.global [%0], [%1], 16;" :: "r"(d), "l"(s));
}
__device__ __forceinline__ void cp_commit() { asm volatile("cp.async.commit_group;"); }
template <int N>
__device__ __forceinline__ void cp_wait() { asm volatile("cp.async.wait_group %0;" :: "n"(N)); }

__device__ __forceinline__ void ldm4(uint32_t r[4], uint32_t addr) {
    asm volatile("ldmatrix.sync.aligned.m8n8.x4.shared.b16 {%0,%1,%2,%3}, [%4];"
                 : "=r"(r[0]), "=r"(r[1]), "=r"(r[2]), "=r"(r[3]) : "r"(addr));
}

// fp16 MMA, fp32 accumulator: m16n8k16
__device__ __forceinline__ void mma16(float c[4], const uint32_t a[4], const uint32_t b[2]) {
    asm volatile(
        "mma.sync.aligned.m16n8k16.row.col.f32.f16.f16.f32 "
        "{%0,%1,%2,%3}, {%4,%5,%6,%7}, {%8,%9}, {%0,%1,%2,%3};"
        : "+f"(c[0]), "+f"(c[1]), "+f"(c[2]), "+f"(c[3])
        : "r"(a[0]), "r"(a[1]), "r"(a[2]), "r"(a[3]), "r"(b[0]), "r"(b[1]));
}

// ============================================================================
// Core: C[128x128] = A[128x512] * B[128x512]^T (fp16 K-major, fp32 acc)
// 4 warps 2(m) x 2(n); warp tile 64x64; acc[4 mfrag][8 nfrag][4]
// (R8-proven version: hoisted load addressing, frag double-buffer, STAGES=3)
// ============================================================================
__device__ __forceinline__ void gemm_core(const __half* __restrict__ Ab,
                                          const __half* __restrict__ Bb,
                                          float acc[4][8][4], char* smem) {
    int tid = threadIdx.x;
    uint32_t smu = s2u(smem);
    int r0 = tid >> 3, seg = tid & 7;

    const __half* aPtr = Ab + (size_t)r0 * DDIM + seg * 8;
    const __half* bPtr = Bb + (size_t)r0 * DDIM + seg * 8;
    uint32_t dstA = smu + (uint32_t)(r0 * 128 + ((seg ^ (r0 & 7)) << 4));
    uint32_t dstB = dstA + BM * 128;

    auto load = [&](int stage, int k0) {
        uint32_t so = (uint32_t)stage * STAGE_BYTES;
#pragma unroll
        for (int t = 0; t < 8; ++t)
            cp16(dstA + so + t * 2048, aPtr + k0 + (size_t)t * 16 * DDIM);
#pragma unroll
        for (int t = 0; t < 8; ++t)
            cp16(dstB + so + t * 2048, bPtr + k0 + (size_t)t * 16 * DDIM);
    };

    load(0, 0);  cp_commit();
    load(1, BK); cp_commit();

    int lane = tid & 31, warp = tid >> 5;
    int wy = warp & 1, wx = warp >> 1;
    int lane7 = lane & 7, sub = lane >> 3;
    int aSel = sub >> 1, bSel = sub & 1;  // which 16B seg (lo/hi of k16) this thread fetches

    // ldmatrix per-thread row bases. row&7 == lane7 for every fragment row.
    uint32_t aBase[4], bBase[4];
#pragma unroll
    for (int i = 0; i < 4; ++i)
        aBase[i] = (uint32_t)(wy * 64 + 16 * i + lane7 + 8 * (sub & 1)) * 128;
#pragma unroll
    for (int jp = 0; jp < 4; ++jp)
        bBase[jp] = (uint32_t)(BM * 128) +
                    (uint32_t)(wx * 64 + 16 * jp + 8 * (sub >> 1) + lane7) * 128;

    int ld = 2, ls = 2, cs = 0;
#pragma unroll 1
    for (int kc = 0; kc < DDIM / BK; ++kc) {
        cp_wait<STAGES - 2>();
        __syncthreads();  // stage kc ready; all warps done with stage being overwritten
        if (ld < DDIM / BK) {
            load(ls, ld * BK);
            ++ld; if (++ls == STAGES) ls = 0;
        }
        cp_commit();
        uint32_t sbu = smu + cs * STAGE_BYTES;
        if (++cs == STAGES) cs = 0;

        uint32_t a[2][4][4], b[2][4][4];
        {
            uint32_t swA = (uint32_t)((aSel ^ lane7) << 4);
            uint32_t swB = (uint32_t)((bSel ^ lane7) << 4);
#pragma unroll
            for (int i = 0; i < 4; ++i) ldm4(a[0][i], sbu + aBase[i] + swA);
#pragma unroll
            for (int jp = 0; jp < 4; ++jp) ldm4(b[0][jp], sbu + bBase[jp] + swB);
        }
#pragma unroll
        for (int ks = 0; ks < 4; ++ks) {
            int cb = ks & 1, nb = cb ^ 1;
            if (ks < 3) {  // prefetch ks+1 fragments; overlaps the MMA block below
                uint32_t swA = (uint32_t)(((2 * (ks + 1) + aSel) ^ lane7) << 4);
                uint32_t swB = (uint32_t)(((2 * (ks + 1) + bSel) ^ lane7) << 4);
#pragma unroll
                for (int i = 0; i < 4; ++i) ldm4(a[nb][i], sbu + aBase[i] + swA);
#pragma unroll
                for (int jp = 0; jp < 4; ++jp) ldm4(b[nb][jp], sbu + bBase[jp] + swB);
            }
#pragma unroll
            for (int i = 0; i < 4; ++i)
#pragma unroll
                for (int j = 0; j < 8; ++j)
                    mma16(acc[i][j], a[cb][i], &b[cb][j >> 1][(j & 1) * 2]);
        }
    }
}

// ============================================================================
// GEMM1: h = gelu(x @ W1^T + b1) -> g_h [P,B,D] fp16  (R15 epilogue, no hints)
// ============================================================================
__global__ void __launch_bounds__(NTH, 2)
gemm1_kernel(const float* __restrict__ b1) {
    extern __shared__ char smem[];
    int p = blockIdx.z, m0 = blockIdx.y * BM, n0 = blockIdx.x * BN;
    const __half* Ab = g_xh + ((size_t)p * BBT + m0) * DDIM;
    const __half* Bb = g_w1 + (size_t)p * DDIM * DDIM + (size_t)n0 * DDIM;

    float acc[4][8][4];
#pragma unroll
    for (int i = 0; i < 4; ++i)
#pragma unroll
        for (int j = 0; j < 8; ++j)
#pragma unroll
            for (int k = 0; k < 4; ++k) acc[i][j][k] = 0.0f;

    gemm_core(Ab, Bb, acc, smem);

    int lane = threadIdx.x & 31, warp = threadIdx.x >> 5;
    int wy = warp & 1, wx = warp >> 1, q = lane >> 2, t4 = lane & 3;
    const float* bias = b1 + p * DDIM + n0 + wx * 64;
#pragma unroll
    for (int i = 0; i < 4; ++i)
#pragma unroll
        for (int h = 0; h < 2; ++h) {
            int row = m0 + wy * 64 + 16 * i + q + 8 * h;  // batch index b
            __half* hrow = g_h + ((size_t)p * BBT + row) * DDIM + n0 + wx * 64;
#pragma unroll
            for (int j = 0; j < 8; ++j) {
                int col = 8 * j + 2 * t4;
                float2 bv = *reinterpret_cast<const float2*>(bias + col);
                float v0 = acc[i][j][2 * h]     + bv.x;
                float v1 = acc[i][j][2 * h + 1] + bv.y;
                float g0 = 0.5f * v0 * (1.0f + erff(v0 * 0.70710678118654752f));
                float g1 = 0.5f * v1 * (1.0f + erff(v1 * 0.70710678118654752f));
                *reinterpret_cast<__half2*>(hrow + col) = __floats2half2_rn(g0, g1);
            }
        }
}

// ============================================================================
// GEMM2: d_out = h @ W2^T + b2 + x (unnormalized), plus per-64col LN stats
// (R15-proven epilogue, no cache hints)
// ============================================================================
__global__ void __launch_bounds__(NTH, 2)
gemm2_kernel(const float* __restrict__ x, const float* __restrict__ b2,
             float* __restrict__ out) {
    extern __shared__ char smem[];
    int p = blockIdx.z, m0 = blockIdx.y * BM, n0 = blockIdx.x * BN;
    const __half* Ab = g_h  + ((size_t)p * BBT + m0) * DDIM;
    const __half* Bb = g_w2 + (size_t)p * DDIM * DDIM + (size_t)n0 * DDIM;

    float acc[4][8][4];
#pragma unroll
    for (int i = 0; i < 4; ++i)
#pragma unroll
        for (int j = 0; j < 8; ++j)
#pragma unroll
            for (int k = 0; k < 4; ++k) acc[i][j][k] = 0.0f;

    gemm_core(Ab, Bb, acc, smem);

    int lane = threadIdx.x & 31, warp = threadIdx.x >> 5;
    int wy = warp & 1, wx = warp >> 1, q = lane >> 2, t4 = lane & 3;
    const float* bias = b2 + p * DDIM + n0 + wx * 64;
    int slice = blockIdx.x * 2 + wx;  // 8 slices of 64 cols per output row
#pragma unroll
    for (int i = 0; i < 4; ++i)
#pragma unroll
        for (int h = 0; h < 2; ++h) {
            int row = m0 + wy * 64 + 16 * i + q + 8 * h;  // batch index b
            size_t ro = (size_t)row * PP + p;             // output row id
            const float* xr = x + ro * DDIM + n0 + wx * 64;
            float* orow = out + ro * DDIM + n0 + wx * 64;
            float s = 0.0f, ss = 0.0f;
#pragma unroll
            for (int j = 0; j < 8; ++j) {
                int col = 8 * j + 2 * t4;
                float2 xv = *reinterpret_cast<const float2*>(xr + col);
                float2 bv = *reinterpret_cast<const float2*>(bias + col);
                float v0 = acc[i][j][2 * h]     + bv.x + xv.x;
                float v1 = acc[i][j][2 * h + 1] + bv.y + xv.y;
                *reinterpret_cast<float2*>(orow + col) = make_float2(v0, v1);
                s += v0 + v1;
                ss += v0 * v0 + v1 * v1;
            }
            s  += __shfl_xor_sync(0xffffffffu, s, 1);
            s  += __shfl_xor_sync(0xffffffffu, s, 2);
            ss += __shfl_xor_sync(0xffffffffu, ss, 1);
            ss += __shfl_xor_sync(0xffffffffu, ss, 2);
            if (t4 == 0) g_stats[ro * 8 + slice] = make_float2(s, ss);
        }
}

// ============================================================================
// LN finalize: normalize d_out in place using precomputed stats.
// .cs hints KEPT here only — measured win in R16 (66.7 -> 64.9us); out rows
// are genuinely dead after this kernel (pipeline end).
// ============================================================================
__global__ void __launch_bounds__(256)
ln_kernel(float* __restrict__ out, const float* __restrict__ gamma,
          const float* __restrict__ beta) {
    int warp = threadIdx.x >> 5, lane = threadIdx.x & 31;
    size_t r = (size_t)blockIdx.x * 8 + warp;
    float s = 0.0f, ss = 0.0f;
    if (lane < 8) {
        float2 st = g_stats[r * 8 + lane];
        s = st.x; ss = st.y;
    }
#pragma unroll
    for (int d = 1; d < 8; d <<= 1) {
        s  += __shfl_xor_sync(0xffffffffu, s, d);
        ss += __shfl_xor_sync(0xffffffffu, ss, d);
    }
    s  = __shfl_sync(0xffffffffu, s, 0);
    ss = __shfl_sync(0xffffffffu, ss, 0);
    float mu = s * (1.0f / 512.0f);
    float rstd = rsqrtf(ss * (1.0f / 512.0f) - mu * mu + 1e-5f);

    float* row = out + r * DDIM;
#pragma unroll
    for (int c = 0; c < 4; ++c) {
        int idx = c * 128 + lane * 4;
        float4 v = __ldcs(reinterpret_cast<const float4*>(row + idx));
        float4 g = *reinterpret_cast<const float4*>(gamma + idx);
        float4 b = *reinterpret_cast<const float4*>(beta + idx);
        float4 o;
        o.x = (v.x - mu) * rstd * g.x + b.x;
        o.y = (v.y - mu) * rstd * g.y + b.y;
        o.z = (v.z - mu) * rstd * g.z + b.z;
        o.w = (v.w - mu) * rstd * g.w + b.w;
        __stcs(reinterpret_cast<float4*>(row + idx), o);
    }
}

// ============================================================================
// Single merged converter: W1/W2 fp32->fp16 and x fp32->fp16 [B,P,D]->[P,B,D].
// (R15 version, no cache hints)
// ============================================================================
__device__ __forceinline__ uint2 pack4h(float4 v) {
    __half2 h01 = __floats2half2_rn(v.x, v.y);
    __half2 h23 = __floats2half2_rn(v.z, v.w);
    uint2 r;
    r.x = *reinterpret_cast<uint32_t*>(&h01);
    r.y = *reinterpret_cast<uint32_t*>(&h23);
    return r;
}

__global__ void cvt_all_kernel(const float4* __restrict__ x4,
                               const float4* __restrict__ w1,
                               const float4* __restrict__ w2) {
    const size_t NW = WE / 4;           // 3,538,944 per W array
    const size_t NX = XT / 4;           // 14,155,776
    size_t total = NW + NX;             // w-pairs first, then x
    size_t stride = (size_t)gridDim.x * blockDim.x;
    for (size_t t = (size_t)blockIdx.x * blockDim.x + threadIdx.x; t < total; t += stride) {
        if (t < NW) {
            *reinterpret_cast<uint2*>(g_w1 + t * 4) = pack4h(w1[t]);
            *reinterpret_cast<uint2*>(g_w2 + t * 4) = pack4h(w2[t]);
        } else {
            size_t u = t - NW;
            size_t d4 = u & (DDIM / 4 - 1);       // 0..127
            size_t b  = (u >> 7) & (BBT - 1);     // 0..2047
            size_t p  = u >> 18;                  // 0..53
            float4 v = x4[(b * PP + p) * (DDIM / 4) + d4];
            *reinterpret_cast<uint2*>(g_xh + (p * BBT + b) * DDIM + d4 * 4) = pack4h(v);
        }
    }
}

// ============================================================================
// kernel_launch
// ============================================================================
extern "C" void kernel_launch(void* const* d_in, const int* in_sizes, int n_in,
                              void* d_out, int out_size) {
    const float* x     = (const float*)d_in[0];
    const float* W1    = (const float*)d_in[1];
    const float* b1    = (const float*)d_in[2];
    const float* W2    = (const float*)d_in[3];
    const float* b2    = (const float*)d_in[4];
    const float* gamma = (const float*)d_in[5];
    const float* beta  = (const float*)d_in[6];
    float* out = (float*)d_out;

    cudaFuncSetAttribute(gemm1_kernel, cudaFuncAttributeMaxDynamicSharedMemorySize, SMEM_BYTES);
    cudaFuncSetAttribute(gemm2_kernel, cudaFuncAttributeMaxDynamicSharedMemorySize, SMEM_BYTES);

    cvt_all_kernel<<<2368, 256>>>(reinterpret_cast<const float4*>(x),
                                  reinterpret_cast<const float4*>(W1),
                                  reinterpret_cast<const float4*>(W2));

    // x fastest = n-tile: 4 CTAs share each A tile; one patch's W (512KB fp16) L2-hot
    dim3 grid(DDIM / BN, BBT / BM, PP);  // (4, 16, 54)
    gemm1_kernel<<<grid, NTH, SMEM_BYTES>>>(b1);
    gemm2_kernel<<<grid, NTH, SMEM_BYTES>>>(x, b2, out);

    ln_kernel<<<(BBT * PP) / 8, 256>>>(out, gamma, beta);
}